// round 11
// baseline (speedup 1.0000x reference)
#include <cuda_runtime.h>

#define D 128
#define K2 64           // number of k-pairs
#define TM 64           // gemm rows per block
#define N_NODES 100000
#define PWR 132         // shW2 row stride in pairs (128 + 4 pad)
#define PZR 66          // shZ2 row stride in pairs (64 + 2 pad)

// Quantized operands for the edge phase (halved gather bytes):
__device__ short g_z16[N_NODES * D];    // z, int16 row-scaled   (25.6 MB)
__device__ short g_wz16[N_NODES * D];   // wz, int16 row-scaled  (25.6 MB)
__device__ float g_sz[N_NODES];         // per-row scale of z
__device__ float g_sw[N_NODES];         // per-row scale of wz
__device__ int   g_idx64;               // 1 if edge_index is int64

#define UNPACK2(lo, hi, in) \
    asm("mov.b64 {%0, %1}, %2;" : "=f"(lo), "=f"(hi) : "l"(in))
#define FMA2(acc, a, b) \
    asm("fma.rn.f32x2 %0, %1, %2, %0;" : "+l"(acc) : "l"(a), "l"(b))

// dp4a variants (mixed signedness for the int16 -> 2x int8 decomposition)
#define DP4A_SS(acc, a, b) \
    asm("dp4a.s32.s32 %0, %1, %2, %0;" : "+r"(acc) : "r"(a), "r"(b))
#define DP4A_SU(acc, a, b) \
    asm("dp4a.s32.u32 %0, %1, %2, %0;" : "+r"(acc) : "r"(a), "r"(b))
#define DP4A_US(acc, a, b) \
    asm("dp4a.u32.s32 %0, %1, %2, %0;" : "+r"(acc) : "r"(a), "r"(b))
#define DP4A_UU(acc, a, b) \
    asm("dp4a.u32.u32 %0, %1, %2, %0;" : "+r"(acc) : "r"(a), "r"(b))
#define PRMT(out, a, b, sel) \
    asm("prmt.b32 %0, %1, %2, %3;" : "=r"(out) : "r"(a), "r"(b), "n"(sel))

__device__ __forceinline__ short q15(float v, float inv) {
    int q = __float2int_rn(v * inv);
    q = max(-32767, min(32767, q));
    return (short)q;
}

// ---------------------------------------------------------------------------
// z quantization: one warp per row (butterfly row-max, int15 scale).
// Block 0 thread 0 also detects edge_index width (int64 samples all lie in
// [0,N); int32 read as int64 packs two indices and only looks valid when the
// high half is 0, p~1e-5/sample; 64 samples -> certain). Deterministic.
// ---------------------------------------------------------------------------
__global__ void __launch_bounds__(256) zquant_kernel(const float* __restrict__ z,
                                                     const long long* __restrict__ ei64,
                                                     int E, int n_rows) {
    if (blockIdx.x == 0 && threadIdx.x == 0) {
        int all_valid = 1;
        const int step = E > 64 ? E / 64 : 1;
        for (int i = 0; i < 64; i++) {
            long long v = ei64[(long long)(i * step) % E];
            if (v < 0 || v >= N_NODES) { all_valid = 0; break; }
        }
        g_idx64 = all_valid;
    }

    const int row = (int)((blockIdx.x * 256u + threadIdx.x) >> 5);
    const int lane = threadIdx.x & 31;
    if (row >= n_rows) return;

    const float4 v = ((const float4*)(z + (size_t)row * D))[lane];
    float m = fmaxf(fmaxf(fabsf(v.x), fabsf(v.y)), fmaxf(fabsf(v.z), fabsf(v.w)));
    #pragma unroll
    for (int off = 16; off > 0; off >>= 1)
        m = fmaxf(m, __shfl_xor_sync(0xffffffffu, m, off));

    const float inv = 32767.0f / fmaxf(m, 1e-30f);
    short4 q;
    q.x = q15(v.x, inv); q.y = q15(v.y, inv);
    q.z = q15(v.z, inv); q.w = q15(v.w, inv);
    ((short4*)(g_z16 + (size_t)row * D))[lane] = q;
    if (lane == 0) g_sz[row] = m * (1.0f / 32767.0f);
}

// ---------------------------------------------------------------------------
// GEMM (k-pair FFMA2 form): wz[n][o] = sum_k z[n][k]*W[o][k] + b[o].
// Both smem operands stored as 8-byte k-pairs (v^{2k2}, v^{2k2+1}), so the
// inner loop is pure LDS.128 + FFMA2 with NO packing movs: each FFMA2
// advances 2 k-steps; accumulators hold (even-k, odd-k) partials folded in
// the epilogue. 256 threads, 64x128 per block, thread tile 8 rows x 4 cols:
// per k2: 2 LDS.128 (4 w-pairs) + 4 LDS.128 (8 z-pairs, warp-broadcast)
// + 32 FFMA2. Epilogue quantizes rows to int16 (per-row warp max).
// ---------------------------------------------------------------------------
__global__ void __launch_bounds__(256, 2) gemm_kernel(const float* __restrict__ z,
                                                      const float* __restrict__ W,
                                                      const float* __restrict__ b,
                                                      int n_rows) {
    extern __shared__ unsigned long long sh2[];
    unsigned long long* shW2 = sh2;               // [K2][PWR] pairs (67.6 KB)
    unsigned long long* shZ2 = sh2 + K2 * PWR;    // [K2][PZR] pairs (33.8 KB)

    const int t = threadIdx.x;
    const int row0 = blockIdx.x * TM;

    // W fill: idx -> k2 = idx&63 (fast), o = idx>>6. Gmem ulonglong reads are
    // coalesced (consecutive k2 within an o row). STS stride PWR pairs.
    const unsigned long long* W2 = (const unsigned long long*)W;
    #pragma unroll 8
    for (int i = 0; i < D * K2 / 256; i++) {
        const int idx = t + i * 256;
        const int k2 = idx & 63, o = idx >> 6;
        shW2[k2 * PWR + o] = W2[o * K2 + k2];
    }
    // Z fill: idx -> k2 = idx&63, r = idx>>6. Gmem coalesced; STS 2-way.
    const unsigned long long* Z2 = (const unsigned long long*)z;
    #pragma unroll 8
    for (int i = 0; i < TM * K2 / 256; i++) {
        const int idx = t + i * 256;
        const int k2 = idx & 63, r = idx >> 6;
        int row = row0 + r; if (row >= n_rows) row = n_rows - 1;
        shZ2[k2 * PZR + r] = Z2[(size_t)row * K2 + k2];
    }
    __syncthreads();

    const int lane = t & 31;
    const int c0 = lane * 4;         // 4 output cols
    const int r0 = (t >> 5) * 8;     // 8 output rows

    unsigned long long acc2[8][4];   // (even-k, odd-k) partial per (r, c)
    #pragma unroll
    for (int r = 0; r < 8; r++)
        #pragma unroll
        for (int c = 0; c < 4; c++) acc2[r][c] = 0ull;

    #pragma unroll 2
    for (int k2 = 0; k2 < K2; k2++) {
        const unsigned long long* wrow = &shW2[k2 * PWR + c0];
        const ulonglong2 wA = *(const ulonglong2*)(wrow);
        const ulonglong2 wB = *(const ulonglong2*)(wrow + 2);
        const unsigned long long wp[4] = {wA.x, wA.y, wB.x, wB.y};

        const unsigned long long* zrow = &shZ2[k2 * PZR + r0];
        const ulonglong2 zA = *(const ulonglong2*)(zrow);
        const ulonglong2 zB = *(const ulonglong2*)(zrow + 2);
        const ulonglong2 zC = *(const ulonglong2*)(zrow + 4);
        const ulonglong2 zD = *(const ulonglong2*)(zrow + 6);
        const unsigned long long zp[8] = {zA.x, zA.y, zB.x, zB.y,
                                          zC.x, zC.y, zD.x, zD.y};

        #pragma unroll
        for (int r = 0; r < 8; r++) {
            FMA2(acc2[r][0], zp[r], wp[0]);
            FMA2(acc2[r][1], zp[r], wp[1]);
            FMA2(acc2[r][2], zp[r], wp[2]);
            FMA2(acc2[r][3], zp[r], wp[3]);
        }
    }

    // Epilogue: fold even/odd partials, add bias, per-row warp max, quantize.
    const float4 bv = *(const float4*)&b[c0];
    float vals[8][4];
    #pragma unroll
    for (int r = 0; r < 8; r++) {
        #pragma unroll
        for (int c = 0; c < 4; c++) {
            float lo, hi;
            UNPACK2(lo, hi, acc2[r][c]);
            vals[r][c] = lo + hi + (&bv.x)[c];
        }
    }

    #pragma unroll
    for (int r = 0; r < 8; r++) {
        float m = fmaxf(fmaxf(fabsf(vals[r][0]), fabsf(vals[r][1])),
                        fmaxf(fabsf(vals[r][2]), fabsf(vals[r][3])));
        #pragma unroll
        for (int off = 16; off > 0; off >>= 1)
            m = fmaxf(m, __shfl_xor_sync(0xffffffffu, m, off));

        const float inv = 32767.0f / fmaxf(m, 1e-30f);
        const int row = row0 + r0 + r;
        if (row < n_rows) {
            short4 q;
            q.x = q15(vals[r][0], inv); q.y = q15(vals[r][1], inv);
            q.z = q15(vals[r][2], inv); q.w = q15(vals[r][3], inv);
            *(short4*)&g_wz16[(size_t)row * D + c0] = q;
            if (lane == 0) g_sw[row] = m * (1.0f / 32767.0f);
        }
    }
}

// ---------------------------------------------------------------------------
// Edge compute: out[e] = sigmoid( sz[src]*sw[dst] * dot(z16[src], wz16[dst]) )
// 8 lanes per edge, 4 edges per warp; lane loads its 32 B segment as 2x
// LDG.128. int16 dot via int8 decomposition:
//   a*b = 65536*ah*bh + 256*(ah*bl + al*bh) + al*bl
// PRMT splits hi(signed)/lo(unsigned) byte planes, 4 dp4a chains, exact
// integer partials, one fp32 combine per lane, 3-level butterfly.
// ---------------------------------------------------------------------------
__global__ void __launch_bounds__(512) edge_kernel(const void* __restrict__ ei_raw,
                                                   float* __restrict__ out,
                                                   int E) {
    const int warp = (int)((blockIdx.x * 512u + threadIdx.x) >> 5);
    const int lane = threadIdx.x & 31;
    const int sub  = lane >> 3;        // edge slot within warp (0..3)
    const int off  = lane & 7;         // segment within row (0..7)

    long long e = (long long)warp * 4 + sub;
    const long long e_clamped = e < E ? e : (long long)E - 1;

    int src, dst;
    if (g_idx64) {
        const long long* ei = (const long long*)ei_raw;
        src = (int)ei[e_clamped];
        dst = (int)ei[(long long)E + e_clamped];
    } else {
        const int* ei = (const int*)ei_raw;
        src = ei[e_clamped];
        dst = ei[E + e_clamped];
    }

    const float sc = g_sz[src] * g_sw[dst];

    const int4* za = (const int4*)(g_z16 + (size_t)src * D);
    const int4* wa = (const int4*)(g_wz16 + (size_t)dst * D);
    const int4 a0 = za[2 * off];
    const int4 a1 = za[2 * off + 1];
    const int4 w0 = wa[2 * off];
    const int4 w1 = wa[2 * off + 1];

    const int areg[8] = {a0.x, a0.y, a0.z, a0.w, a1.x, a1.y, a1.z, a1.w};
    const int wreg[8] = {w0.x, w0.y, w0.z, w0.w, w1.x, w1.y, w1.z, w1.w};

    int hh = 0, hl = 0, lh = 0, ll = 0;
    #pragma unroll
    for (int p = 0; p < 4; p++) {
        int ah, al, bh, bl;
        PRMT(ah, areg[2 * p], areg[2 * p + 1], 0x7531);
        PRMT(al, areg[2 * p], areg[2 * p + 1], 0x6420);
        PRMT(bh, wreg[2 * p], wreg[2 * p + 1], 0x7531);
        PRMT(bl, wreg[2 * p], wreg[2 * p + 1], 0x6420);
        DP4A_SS(hh, ah, bh);
        DP4A_SU(hl, ah, bl);
        DP4A_US(lh, al, bh);
        DP4A_UU(ll, al, bl);
    }

    float s = 65536.0f * (float)hh;
    s = fmaf(256.0f, (float)(hl + lh), s);
    s += (float)ll;

    s += __shfl_xor_sync(0xffffffffu, s, 4);
    s += __shfl_xor_sync(0xffffffffu, s, 2);
    s += __shfl_xor_sync(0xffffffffu, s, 1);

    if (off == 0 && e < E)
        out[e] = 1.0f / (1.0f + __expf(-s * sc));
}

// ---------------------------------------------------------------------------
// Launch. Inputs: z [N*D f32], edge_index [2*E int32-or-int64], W [D*D], b [D].
// Output: [E] f32.
// ---------------------------------------------------------------------------
extern "C" void kernel_launch(void* const* d_in, const int* in_sizes, int n_in,
                              void* d_out, int out_size) {
    const float* z  = (const float*)d_in[0];
    const void*  ei = d_in[1];
    const float* W  = (const float*)d_in[2];
    const float* b  = (const float*)d_in[3];
    float* out = (float*)d_out;

    const int E = out_size;
    const int n_rows = in_sizes[0] / D;

    zquant_kernel<<<(n_rows * 32 + 255) / 256, 256>>>(z, (const long long*)ei, E, n_rows);

    const int smem = (K2 * PWR + K2 * PZR) * 8;   // ~101.4 KB
    cudaFuncSetAttribute(gemm_kernel, cudaFuncAttributeMaxDynamicSharedMemorySize, smem);
    gemm_kernel<<<(n_rows + TM - 1) / TM, 256, smem>>>(z, W, b, n_rows);

    const int warps_needed = (E + 3) / 4;               // 4 edges per warp
    const int blocks = (warps_needed + 15) / 16;        // 16 warps per block
    edge_kernel<<<blocks, 512>>>(ei, out, E);
}

// round 12
// speedup vs baseline: 1.0448x; 1.0448x over previous
#include <cuda_runtime.h>

#define D 128
#define TM 64           // gemm rows per block
#define N_NODES 100000

// Quantized operands for the edge phase (halved gather bytes):
__device__ short g_z16[N_NODES * D];    // z, int16 row-scaled   (25.6 MB)
__device__ short g_wz16[N_NODES * D];   // wz, int16 row-scaled  (25.6 MB)
__device__ float g_sz[N_NODES];         // per-row scale of z
__device__ float g_sw[N_NODES];         // per-row scale of wz
__device__ int   g_idx64;               // 1 if edge_index is int64

// Packed fp32x2 helpers
#define PACK2(out, lo, hi) \
    asm("mov.b64 %0, {%1, %2};" : "=l"(out) : "f"(lo), "f"(hi))
#define UNPACK2(lo, hi, in) \
    asm("mov.b64 {%0, %1}, %2;" : "=f"(lo), "=f"(hi) : "l"(in))
#define FMA2(acc, a, b) \
    asm("fma.rn.f32x2 %0, %1, %2, %0;" : "+l"(acc) : "l"(a), "l"(b))

// dp4a variants (mixed signedness for the int16 -> 2x int8 decomposition)
#define DP4A_SS(acc, a, b) \
    asm("dp4a.s32.s32 %0, %1, %2, %0;" : "+r"(acc) : "r"(a), "r"(b))
#define DP4A_SU(acc, a, b) \
    asm("dp4a.s32.u32 %0, %1, %2, %0;" : "+r"(acc) : "r"(a), "r"(b))
#define DP4A_US(acc, a, b) \
    asm("dp4a.u32.s32 %0, %1, %2, %0;" : "+r"(acc) : "r"(a), "r"(b))
#define DP4A_UU(acc, a, b) \
    asm("dp4a.u32.u32 %0, %1, %2, %0;" : "+r"(acc) : "r"(a), "r"(b))
#define PRMT(out, a, b, sel) \
    asm("prmt.b32 %0, %1, %2, %3;" : "=r"(out) : "r"(a), "r"(b), "n"(sel))

__device__ __forceinline__ short q15(float v, float inv) {
    int q = __float2int_rn(v * inv);
    q = max(-32767, min(32767, q));
    return (short)q;
}

// ---------------------------------------------------------------------------
// GEMM + both quantizations, one kernel:
//   wz[n][o] = sum_k z[n][k]*W[o][k] + b[o] -> int16 row-scaled (epilogue)
//   z row-quant sourced FROM shZ (already staged; z read once from DRAM).
// 256 threads, 64x128 per block, thread tile 8x4, fma.rn.f32x2 inner loop
// over row pairs (R10 form: z pairs loaded directly as ulonglong2, only the
// 4 w-broadcast packs per k).
// z-quant: warp w owns rows w*8..w*8+7; lane reads shZ[k*68+r] at
// k = lane+{0,32,64,96} (lane stride 68 words = 4 mod 32 -> 4-way conflict,
// NOT the 16-way of a float4-per-lane row gather). Butterfly row max,
// quantize, coalesced STG.16 (32 consecutive shorts per request).
// Block 0 thread 0 detects edge_index width (int64 samples all lie in [0,N);
// int32 read as int64 packs two indices and only looks valid when the high
// half is 0, p~1e-5/sample; 64 samples -> certain). Deterministic.
// ---------------------------------------------------------------------------
__global__ void __launch_bounds__(256, 2) gemm_kernel(const float* __restrict__ z,
                                                      const float* __restrict__ W,
                                                      const float* __restrict__ b,
                                                      const long long* __restrict__ ei64,
                                                      int E, int n_rows) {
    extern __shared__ float sh[];
    float* shW = sh;                 // [128][132] k-major
    float* shZ = sh + D * 132;       // [128][68]  k-major

    const int t = threadIdx.x;
    const int row0 = blockIdx.x * TM;

    if (blockIdx.x == 0 && t == 0) {
        int all_valid = 1;
        const int step = E > 64 ? E / 64 : 1;
        for (int i = 0; i < 64; i++) {
            long long v = ei64[(long long)(i * step) % E];
            if (v < 0 || v >= N_NODES) { all_valid = 0; break; }
        }
        g_idx64 = all_valid;
    }

    #pragma unroll 8
    for (int i = 0; i < D * D / 256; i++) {
        const int idx = t + i * 256;
        shW[(idx & 127) * 132 + (idx >> 7)] = W[idx];
    }
    #pragma unroll 8
    for (int i = 0; i < TM * D / 256; i++) {
        const int idx = t + i * 256;
        const int r = idx >> 7, k = idx & 127;
        int row = row0 + r; if (row >= n_rows) row = n_rows - 1;
        shZ[k * 68 + r] = z[(size_t)row * D + k];
    }
    __syncthreads();

    const int lane = t & 31;
    const int wrp = t >> 5;
    const int c0 = lane * 4;
    const int r0 = wrp * 8;

    // --- z-quant from smem (warp-per-row, 8 rows per warp) ---
    #pragma unroll
    for (int rr = 0; rr < 8; rr++) {
        const int r = r0 + rr;
        const float v0 = shZ[lane * 68 + r];
        const float v1 = shZ[(lane + 32) * 68 + r];
        const float v2 = shZ[(lane + 64) * 68 + r];
        const float v3 = shZ[(lane + 96) * 68 + r];
        float m = fmaxf(fmaxf(fabsf(v0), fabsf(v1)), fmaxf(fabsf(v2), fabsf(v3)));
        #pragma unroll
        for (int off = 16; off > 0; off >>= 1)
            m = fmaxf(m, __shfl_xor_sync(0xffffffffu, m, off));

        const int row = row0 + r;
        if (row < n_rows) {
            const float inv = 32767.0f / fmaxf(m, 1e-30f);
            short* zr = g_z16 + (size_t)row * D;
            zr[lane]      = q15(v0, inv);
            zr[lane + 32] = q15(v1, inv);
            zr[lane + 64] = q15(v2, inv);
            zr[lane + 96] = q15(v3, inv);
            if (lane == 0) g_sz[row] = m * (1.0f / 32767.0f);
        }
    }

    // --- main FFMA2 loop (R10 form) ---
    unsigned long long acc2[4][4];
    #pragma unroll
    for (int rp = 0; rp < 4; rp++)
        #pragma unroll
        for (int c = 0; c < 4; c++) acc2[rp][c] = 0ull;

    #pragma unroll 4
    for (int k = 0; k < D; k++) {
        const float4 wv = *(const float4*)&shW[k * 132 + c0];
        const ulonglong2 zA = *(const ulonglong2*)&shZ[k * 68 + r0];
        const ulonglong2 zB = *(const ulonglong2*)&shZ[k * 68 + r0 + 4];
        const unsigned long long zp[4] = {zA.x, zA.y, zB.x, zB.y};

        unsigned long long ww[4];
        PACK2(ww[0], wv.x, wv.x);
        PACK2(ww[1], wv.y, wv.y);
        PACK2(ww[2], wv.z, wv.z);
        PACK2(ww[3], wv.w, wv.w);

        #pragma unroll
        for (int rp = 0; rp < 4; rp++) {
            FMA2(acc2[rp][0], zp[rp], ww[0]);
            FMA2(acc2[rp][1], zp[rp], ww[1]);
            FMA2(acc2[rp][2], zp[rp], ww[2]);
            FMA2(acc2[rp][3], zp[rp], ww[3]);
        }
    }

    // --- wz epilogue: bias, per-row warp max, int16 quantize ---
    const float4 bv = *(const float4*)&b[c0];
    float vals[8][4];
    #pragma unroll
    for (int rp = 0; rp < 4; rp++) {
        float lo[4], hi[4];
        #pragma unroll
        for (int c = 0; c < 4; c++) UNPACK2(lo[c], hi[c], acc2[rp][c]);
        vals[2 * rp][0] = lo[0] + bv.x; vals[2 * rp][1] = lo[1] + bv.y;
        vals[2 * rp][2] = lo[2] + bv.z; vals[2 * rp][3] = lo[3] + bv.w;
        vals[2 * rp + 1][0] = hi[0] + bv.x; vals[2 * rp + 1][1] = hi[1] + bv.y;
        vals[2 * rp + 1][2] = hi[2] + bv.z; vals[2 * rp + 1][3] = hi[3] + bv.w;
    }

    #pragma unroll
    for (int r = 0; r < 8; r++) {
        float m = fmaxf(fmaxf(fabsf(vals[r][0]), fabsf(vals[r][1])),
                        fmaxf(fabsf(vals[r][2]), fabsf(vals[r][3])));
        #pragma unroll
        for (int off = 16; off > 0; off >>= 1)
            m = fmaxf(m, __shfl_xor_sync(0xffffffffu, m, off));

        const float inv = 32767.0f / fmaxf(m, 1e-30f);
        const int row = row0 + r0 + r;
        if (row < n_rows) {
            short4 q;
            q.x = q15(vals[r][0], inv); q.y = q15(vals[r][1], inv);
            q.z = q15(vals[r][2], inv); q.w = q15(vals[r][3], inv);
            *(short4*)&g_wz16[(size_t)row * D + c0] = q;
            if (lane == 0) g_sw[row] = m * (1.0f / 32767.0f);
        }
    }
}

// ---------------------------------------------------------------------------
// Edge compute: out[e] = sigmoid( sz[src]*sw[dst] * dot(z16[src], wz16[dst]) )
// 8 lanes per edge, 4 edges per warp; lane loads its 32 B segment as 2x
// LDG.128. int16 dot via int8 decomposition:
//   a*b = 65536*ah*bh + 256*(ah*bl + al*bh) + al*bl
// PRMT splits hi(signed)/lo(unsigned) byte planes, 4 dp4a chains, exact
// integer partials, one fp32 combine per lane, 3-level butterfly.
// ---------------------------------------------------------------------------
__global__ void __launch_bounds__(512) edge_kernel(const void* __restrict__ ei_raw,
                                                   float* __restrict__ out,
                                                   int E) {
    const int warp = (int)((blockIdx.x * 512u + threadIdx.x) >> 5);
    const int lane = threadIdx.x & 31;
    const int sub  = lane >> 3;        // edge slot within warp (0..3)
    const int off  = lane & 7;         // segment within row (0..7)

    long long e = (long long)warp * 4 + sub;
    const long long e_clamped = e < E ? e : (long long)E - 1;

    int src, dst;
    if (g_idx64) {
        const long long* ei = (const long long*)ei_raw;
        src = (int)ei[e_clamped];
        dst = (int)ei[(long long)E + e_clamped];
    } else {
        const int* ei = (const int*)ei_raw;
        src = ei[e_clamped];
        dst = ei[E + e_clamped];
    }

    const float sc = g_sz[src] * g_sw[dst];

    const int4* za = (const int4*)(g_z16 + (size_t)src * D);
    const int4* wa = (const int4*)(g_wz16 + (size_t)dst * D);
    const int4 a0 = za[2 * off];
    const int4 a1 = za[2 * off + 1];
    const int4 w0 = wa[2 * off];
    const int4 w1 = wa[2 * off + 1];

    const int areg[8] = {a0.x, a0.y, a0.z, a0.w, a1.x, a1.y, a1.z, a1.w};
    const int wreg[8] = {w0.x, w0.y, w0.z, w0.w, w1.x, w1.y, w1.z, w1.w};

    int hh = 0, hl = 0, lh = 0, ll = 0;
    #pragma unroll
    for (int p = 0; p < 4; p++) {
        int ah, al, bh, bl;
        PRMT(ah, areg[2 * p], areg[2 * p + 1], 0x7531);
        PRMT(al, areg[2 * p], areg[2 * p + 1], 0x6420);
        PRMT(bh, wreg[2 * p], wreg[2 * p + 1], 0x7531);
        PRMT(bl, wreg[2 * p], wreg[2 * p + 1], 0x6420);
        DP4A_SS(hh, ah, bh);
        DP4A_SU(hl, ah, bl);
        DP4A_US(lh, al, bh);
        DP4A_UU(ll, al, bl);
    }

    float s = 65536.0f * (float)hh;
    s = fmaf(256.0f, (float)(hl + lh), s);
    s += (float)ll;

    s += __shfl_xor_sync(0xffffffffu, s, 4);
    s += __shfl_xor_sync(0xffffffffu, s, 2);
    s += __shfl_xor_sync(0xffffffffu, s, 1);

    if (off == 0 && e < E)
        out[e] = 1.0f / (1.0f + __expf(-s * sc));
}

// ---------------------------------------------------------------------------
// Launch. Inputs: z [N*D f32], edge_index [2*E int32-or-int64], W [D*D], b [D].
// Output: [E] f32.
// ---------------------------------------------------------------------------
extern "C" void kernel_launch(void* const* d_in, const int* in_sizes, int n_in,
                              void* d_out, int out_size) {
    const float* z  = (const float*)d_in[0];
    const void*  ei = d_in[1];
    const float* W  = (const float*)d_in[2];
    const float* b  = (const float*)d_in[3];
    float* out = (float*)d_out;

    const int E = out_size;
    const int n_rows = in_sizes[0] / D;

    const int smem = (D * 132 + D * 68) * (int)sizeof(float);   // ~102.4 KB
    cudaFuncSetAttribute(gemm_kernel, cudaFuncAttributeMaxDynamicSharedMemorySize, smem);
    gemm_kernel<<<(n_rows + TM - 1) / TM, 256, smem>>>(z, W, b,
                                                       (const long long*)ei, E, n_rows);

    const int warps_needed = (E + 3) / 4;               // 4 edges per warp
    const int blocks = (warps_needed + 15) / 16;        // 16 warps per block
    edge_kernel<<<blocks, 512>>>(ei, out, E);
}

// round 13
// speedup vs baseline: 1.0582x; 1.0128x over previous
#include <cuda_runtime.h>

#define D 128
#define TM 64           // gemm rows per block
#define N_NODES 100000

// Quantized operands for the edge phase (halved gather bytes):
__device__ short g_z16[N_NODES * D];    // z, int16 row-scaled   (25.6 MB)
__device__ short g_wz16[N_NODES * D];   // wz, int16 row-scaled  (25.6 MB)
__device__ float g_sz[N_NODES];         // per-row scale of z
__device__ float g_sw[N_NODES];         // per-row scale of wz
__device__ int   g_idx64;               // 1 if edge_index is int64

// Packed fp32x2 helpers
#define PACK2(out, lo, hi) \
    asm("mov.b64 %0, {%1, %2};" : "=l"(out) : "f"(lo), "f"(hi))
#define UNPACK2(lo, hi, in) \
    asm("mov.b64 {%0, %1}, %2;" : "=f"(lo), "=f"(hi) : "l"(in))
#define FMA2(acc, a, b) \
    asm("fma.rn.f32x2 %0, %1, %2, %0;" : "+l"(acc) : "l"(a), "l"(b))

// dp4a variants (mixed signedness for the int16 -> 2x int8 decomposition)
#define DP4A_SS(acc, a, b) \
    asm("dp4a.s32.s32 %0, %1, %2, %0;" : "+r"(acc) : "r"(a), "r"(b))
#define DP4A_SU(acc, a, b) \
    asm("dp4a.s32.u32 %0, %1, %2, %0;" : "+r"(acc) : "r"(a), "r"(b))
#define DP4A_US(acc, a, b) \
    asm("dp4a.u32.s32 %0, %1, %2, %0;" : "+r"(acc) : "r"(a), "r"(b))
#define DP4A_UU(acc, a, b) \
    asm("dp4a.u32.u32 %0, %1, %2, %0;" : "+r"(acc) : "r"(a), "r"(b))
#define PRMT(out, a, b, sel) \
    asm("prmt.b32 %0, %1, %2, %3;" : "=r"(out) : "r"(a), "r"(b), "n"(sel))

__device__ __forceinline__ short q15(float v, float inv) {
    int q = __float2int_rn(v * inv);
    q = max(-32767, min(32767, q));
    return (short)q;
}

// ---------------------------------------------------------------------------
// z quantization: one warp per row (butterfly row-max, int15 scale).
// Block 0 thread 0 also detects edge_index width (int64 samples all lie in
// [0,N); int32 read as int64 packs two indices and only looks valid when the
// high half is 0, p~1e-5/sample; 64 samples -> certain). Deterministic.
// Runs CONCURRENTLY with the GEMM (parallel graph branch) -- it writes only
// g_z16/g_sz/g_idx64, which the GEMM never touches.
// ---------------------------------------------------------------------------
__global__ void __launch_bounds__(256) zquant_kernel(const float* __restrict__ z,
                                                     const long long* __restrict__ ei64,
                                                     int E, int n_rows) {
    if (blockIdx.x == 0 && threadIdx.x == 0) {
        int all_valid = 1;
        const int step = E > 64 ? E / 64 : 1;
        for (int i = 0; i < 64; i++) {
            long long v = ei64[(long long)(i * step) % E];
            if (v < 0 || v >= N_NODES) { all_valid = 0; break; }
        }
        g_idx64 = all_valid;
    }

    const int row = (int)((blockIdx.x * 256u + threadIdx.x) >> 5);
    const int lane = threadIdx.x & 31;
    if (row >= n_rows) return;

    const float4 v = ((const float4*)(z + (size_t)row * D))[lane];
    float m = fmaxf(fmaxf(fabsf(v.x), fabsf(v.y)), fmaxf(fabsf(v.z), fabsf(v.w)));
    #pragma unroll
    for (int off = 16; off > 0; off >>= 1)
        m = fmaxf(m, __shfl_xor_sync(0xffffffffu, m, off));

    const float inv = 32767.0f / fmaxf(m, 1e-30f);
    short4 q;
    q.x = q15(v.x, inv); q.y = q15(v.y, inv);
    q.z = q15(v.z, inv); q.w = q15(v.w, inv);
    ((short4*)(g_z16 + (size_t)row * D))[lane] = q;
    if (lane == 0) g_sz[row] = m * (1.0f / 32767.0f);
}

// ---------------------------------------------------------------------------
// GEMM (proven R10 form): wz[n][o] = sum_k z[n][k]*W[o][k] + b[o], epilogue
// quantizes rows to int16. 256 threads, 64x128 per block, thread tile 8x4,
// fma.rn.f32x2 inner loop over row pairs; z pairs loaded directly as
// ulonglong2 (no packing movs), only 4 w-broadcast packs per k.
// ---------------------------------------------------------------------------
__global__ void __launch_bounds__(256, 2) gemm_kernel(const float* __restrict__ z,
                                                      const float* __restrict__ W,
                                                      const float* __restrict__ b,
                                                      int n_rows) {
    extern __shared__ float sh[];
    float* shW = sh;                 // [128][132] k-major
    float* shZ = sh + D * 132;       // [128][68]  k-major

    const int t = threadIdx.x;
    const int row0 = blockIdx.x * TM;

    #pragma unroll 8
    for (int i = 0; i < D * D / 256; i++) {
        const int idx = t + i * 256;
        shW[(idx & 127) * 132 + (idx >> 7)] = W[idx];
    }
    #pragma unroll 8
    for (int i = 0; i < TM * D / 256; i++) {
        const int idx = t + i * 256;
        const int r = idx >> 7, k = idx & 127;
        int row = row0 + r; if (row >= n_rows) row = n_rows - 1;
        shZ[k * 68 + r] = z[(size_t)row * D + k];
    }
    __syncthreads();

    const int lane = t & 31;
    const int c0 = lane * 4;
    const int r0 = (t >> 5) * 8;

    unsigned long long acc2[4][4];
    #pragma unroll
    for (int rp = 0; rp < 4; rp++)
        #pragma unroll
        for (int c = 0; c < 4; c++) acc2[rp][c] = 0ull;

    #pragma unroll 4
    for (int k = 0; k < D; k++) {
        const float4 wv = *(const float4*)&shW[k * 132 + c0];
        const ulonglong2 zA = *(const ulonglong2*)&shZ[k * 68 + r0];
        const ulonglong2 zB = *(const ulonglong2*)&shZ[k * 68 + r0 + 4];
        const unsigned long long zp[4] = {zA.x, zA.y, zB.x, zB.y};

        unsigned long long ww[4];
        PACK2(ww[0], wv.x, wv.x);
        PACK2(ww[1], wv.y, wv.y);
        PACK2(ww[2], wv.z, wv.z);
        PACK2(ww[3], wv.w, wv.w);

        #pragma unroll
        for (int rp = 0; rp < 4; rp++) {
            FMA2(acc2[rp][0], zp[rp], ww[0]);
            FMA2(acc2[rp][1], zp[rp], ww[1]);
            FMA2(acc2[rp][2], zp[rp], ww[2]);
            FMA2(acc2[rp][3], zp[rp], ww[3]);
        }
    }

    const float4 bv = *(const float4*)&b[c0];
    float vals[8][4];
    #pragma unroll
    for (int rp = 0; rp < 4; rp++) {
        float lo[4], hi[4];
        #pragma unroll
        for (int c = 0; c < 4; c++) UNPACK2(lo[c], hi[c], acc2[rp][c]);
        vals[2 * rp][0] = lo[0] + bv.x; vals[2 * rp][1] = lo[1] + bv.y;
        vals[2 * rp][2] = lo[2] + bv.z; vals[2 * rp][3] = lo[3] + bv.w;
        vals[2 * rp + 1][0] = hi[0] + bv.x; vals[2 * rp + 1][1] = hi[1] + bv.y;
        vals[2 * rp + 1][2] = hi[2] + bv.z; vals[2 * rp + 1][3] = hi[3] + bv.w;
    }

    #pragma unroll
    for (int r = 0; r < 8; r++) {
        float m = fmaxf(fmaxf(fabsf(vals[r][0]), fabsf(vals[r][1])),
                        fmaxf(fabsf(vals[r][2]), fabsf(vals[r][3])));
        #pragma unroll
        for (int off = 16; off > 0; off >>= 1)
            m = fmaxf(m, __shfl_xor_sync(0xffffffffu, m, off));

        const float inv = 32767.0f / fmaxf(m, 1e-30f);
        const int row = row0 + r0 + r;
        if (row < n_rows) {
            short4 q;
            q.x = q15(vals[r][0], inv); q.y = q15(vals[r][1], inv);
            q.z = q15(vals[r][2], inv); q.w = q15(vals[r][3], inv);
            *(short4*)&g_wz16[(size_t)row * D + c0] = q;
            if (lane == 0) g_sw[row] = m * (1.0f / 32767.0f);
        }
    }
}

// ---------------------------------------------------------------------------
// Edge compute: out[e] = sigmoid( sz[src]*sw[dst] * dot(z16[src], wz16[dst]) )
// 8 lanes per edge, 4 edges per warp; lane loads its 32 B segment as 2x
// LDG.128. int16 dot via int8 decomposition:
//   a*b = 65536*ah*bh + 256*(ah*bl + al*bh) + al*bl
// PRMT splits hi(signed)/lo(unsigned) byte planes, 4 dp4a chains, exact
// integer partials, one fp32 combine per lane, 3-level butterfly.
// ---------------------------------------------------------------------------
__global__ void __launch_bounds__(512) edge_kernel(const void* __restrict__ ei_raw,
                                                   float* __restrict__ out,
                                                   int E) {
    const int warp = (int)((blockIdx.x * 512u + threadIdx.x) >> 5);
    const int lane = threadIdx.x & 31;
    const int sub  = lane >> 3;        // edge slot within warp (0..3)
    const int off  = lane & 7;         // segment within row (0..7)

    long long e = (long long)warp * 4 + sub;
    const long long e_clamped = e < E ? e : (long long)E - 1;

    int src, dst;
    if (g_idx64) {
        const long long* ei = (const long long*)ei_raw;
        src = (int)ei[e_clamped];
        dst = (int)ei[(long long)E + e_clamped];
    } else {
        const int* ei = (const int*)ei_raw;
        src = ei[e_clamped];
        dst = ei[E + e_clamped];
    }

    const float sc = g_sz[src] * g_sw[dst];

    const int4* za = (const int4*)(g_z16 + (size_t)src * D);
    const int4* wa = (const int4*)(g_wz16 + (size_t)dst * D);
    const int4 a0 = za[2 * off];
    const int4 a1 = za[2 * off + 1];
    const int4 w0 = wa[2 * off];
    const int4 w1 = wa[2 * off + 1];

    const int areg[8] = {a0.x, a0.y, a0.z, a0.w, a1.x, a1.y, a1.z, a1.w};
    const int wreg[8] = {w0.x, w0.y, w0.z, w0.w, w1.x, w1.y, w1.z, w1.w};

    int hh = 0, hl = 0, lh = 0, ll = 0;
    #pragma unroll
    for (int p = 0; p < 4; p++) {
        int ah, al, bh, bl;
        PRMT(ah, areg[2 * p], areg[2 * p + 1], 0x7531);
        PRMT(al, areg[2 * p], areg[2 * p + 1], 0x6420);
        PRMT(bh, wreg[2 * p], wreg[2 * p + 1], 0x7531);
        PRMT(bl, wreg[2 * p], wreg[2 * p + 1], 0x6420);
        DP4A_SS(hh, ah, bh);
        DP4A_SU(hl, ah, bl);
        DP4A_US(lh, al, bh);
        DP4A_UU(ll, al, bl);
    }

    float s = 65536.0f * (float)hh;
    s = fmaf(256.0f, (float)(hl + lh), s);
    s += (float)ll;

    s += __shfl_xor_sync(0xffffffffu, s, 4);
    s += __shfl_xor_sync(0xffffffffu, s, 2);
    s += __shfl_xor_sync(0xffffffffu, s, 1);

    if (off == 0 && e < E)
        out[e] = 1.0f / (1.0f + __expf(-s * sc));
}

// ---------------------------------------------------------------------------
// Launch with a parallel graph branch: zquant (DRAM-bound) runs concurrently
// with gemm (FMA/smem-bound) -- disjoint outputs; edge joins both.
//   main:  [fork ev] --------- gemm ---------- [wait ev2] -> edge
//   side:  [wait ev] -> zquant -> [record ev2]
// Streams/events are created and destroyed per call (host-side only; the
// captured graph keeps its own structure). Same captured work every call.
// ---------------------------------------------------------------------------
extern "C" void kernel_launch(void* const* d_in, const int* in_sizes, int n_in,
                              void* d_out, int out_size) {
    const float* z  = (const float*)d_in[0];
    const void*  ei = d_in[1];
    const float* W  = (const float*)d_in[2];
    const float* b  = (const float*)d_in[3];
    float* out = (float*)d_out;

    const int E = out_size;
    const int n_rows = in_sizes[0] / D;

    cudaStream_t s2;
    cudaStreamCreateWithFlags(&s2, cudaStreamNonBlocking);
    cudaEvent_t ev_fork, ev_join;
    cudaEventCreateWithFlags(&ev_fork, cudaEventDisableTiming);
    cudaEventCreateWithFlags(&ev_join, cudaEventDisableTiming);

    // Fork: side stream joins the (capturing) default stream.
    cudaEventRecord(ev_fork, 0);
    cudaStreamWaitEvent(s2, ev_fork, 0);

    // Side branch: z quantization + idx-width detect.
    zquant_kernel<<<(n_rows * 32 + 255) / 256, 256, 0, s2>>>(
        z, (const long long*)ei, E, n_rows);
    cudaEventRecord(ev_join, s2);

    // Main branch: GEMM (independent of zquant outputs).
    const int smem = (D * 132 + D * 68) * (int)sizeof(float);   // ~102.4 KB
    cudaFuncSetAttribute(gemm_kernel, cudaFuncAttributeMaxDynamicSharedMemorySize, smem);
    gemm_kernel<<<(n_rows + TM - 1) / TM, 256, smem>>>(z, W, b, n_rows);

    // Join: edge needs both branches.
    cudaStreamWaitEvent(0, ev_join, 0);

    const int warps_needed = (E + 3) / 4;               // 4 edges per warp
    const int blocks = (warps_needed + 15) / 16;        // 16 warps per block
    edge_kernel<<<blocks, 512>>>(ei, out, E);

    cudaEventDestroy(ev_fork);
    cudaEventDestroy(ev_join);
    cudaStreamDestroy(s2);
}